// round 1
// baseline (speedup 1.0000x reference)
#include <cuda_runtime.h>
#include <math.h>

#define N   384
#define C   128
#define H   4
#define DH  32
#define NN  (N*N)
#define KV_STRIDE 33

// Scratch (allocation-free rule: __device__ globals)
__device__ float g_x[NN*C];
__device__ float g_q[NN*C];
__device__ float g_k[NN*C];
__device__ float g_v[NN*C];
__device__ float g_g[NN*C];
__device__ float g_o[NN*C];
__device__ float g_bias[H*NN];

// ---------------------------------------------------------------------------
// LayerNorm over C + per-head pair bias. One warp per (q,k) row.
// ---------------------------------------------------------------------------
__global__ void ln_bias_kernel(const float* __restrict__ pair,
                               const float* __restrict__ ln_w,
                               const float* __restrict__ ln_b,
                               const float* __restrict__ w_bias) {
    int warp = threadIdx.x >> 5, lane = threadIdx.x & 31;
    int row = blockIdx.x * 8 + warp;             // row = q*N + k
    const float* p = pair + (size_t)row * C;
    float x0 = p[lane], x1 = p[lane+32], x2 = p[lane+64], x3 = p[lane+96];
    float s = x0 + x1 + x2 + x3;
    #pragma unroll
    for (int o = 16; o; o >>= 1) s += __shfl_xor_sync(0xffffffffu, s, o);
    float mu = s * (1.0f / C);
    float d0 = x0-mu, d1 = x1-mu, d2 = x2-mu, d3 = x3-mu;
    float s2 = d0*d0 + d1*d1 + d2*d2 + d3*d3;
    #pragma unroll
    for (int o = 16; o; o >>= 1) s2 += __shfl_xor_sync(0xffffffffu, s2, o);
    float rstd = rsqrtf(s2 * (1.0f / C) + 1e-5f);
    x0 = d0*rstd*ln_w[lane]    + ln_b[lane];
    x1 = d1*rstd*ln_w[lane+32] + ln_b[lane+32];
    x2 = d2*rstd*ln_w[lane+64] + ln_b[lane+64];
    x3 = d3*rstd*ln_w[lane+96] + ln_b[lane+96];
    float* xo = g_x + (size_t)row * C;
    xo[lane] = x0; xo[lane+32] = x1; xo[lane+64] = x2; xo[lane+96] = x3;
    #pragma unroll
    for (int h = 0; h < H; h++) {
        float bs = x0*w_bias[lane*H + h]      + x1*w_bias[(lane+32)*H + h]
                 + x2*w_bias[(lane+64)*H + h] + x3*w_bias[(lane+96)*H + h];
        #pragma unroll
        for (int o = 16; o; o >>= 1) bs += __shfl_xor_sync(0xffffffffu, bs, o);
        if (lane == 0) g_bias[h*NN + row] = bs;
    }
}

// ---------------------------------------------------------------------------
// [M x 128] @ [128 x 128] tiled SGEMM. Block tile: 32 rows x 64 cols, full K.
// Optional elementwise A-multiplier (gate) and sigmoid post-op.
// ---------------------------------------------------------------------------
__global__ void gemm128_kernel(const float* __restrict__ A,
                               const float* __restrict__ A2,
                               const float* __restrict__ W,
                               float* __restrict__ Out, int sig) {
    __shared__ float As[32 * 128];
    __shared__ float Ws[128 * 64];
    int rowBase = blockIdx.x * 32;
    int colBase = blockIdx.y * 64;
    int tid = threadIdx.x;
    const float* Ap = A + (size_t)rowBase * C;
    if (A2) {
        const float* A2p = A2 + (size_t)rowBase * C;
        #pragma unroll
        for (int i = tid; i < 32*128; i += 256) As[i] = Ap[i] * A2p[i];
    } else {
        #pragma unroll
        for (int i = tid; i < 32*128; i += 256) As[i] = Ap[i];
    }
    #pragma unroll
    for (int i = tid; i < 128*64; i += 256)
        Ws[i] = W[(i >> 6) * C + colBase + (i & 63)];
    __syncthreads();

    int tx = tid & 15, ty = tid >> 4;
    float acc[2][4] = {{0,0,0,0},{0,0,0,0}};
    #pragma unroll 8
    for (int k = 0; k < 128; k++) {
        float a0 = As[(ty*2 + 0)*128 + k];
        float a1 = As[(ty*2 + 1)*128 + k];
        float4 b = *(const float4*)&Ws[k*64 + tx*4];
        acc[0][0] += a0*b.x; acc[0][1] += a0*b.y; acc[0][2] += a0*b.z; acc[0][3] += a0*b.w;
        acc[1][0] += a1*b.x; acc[1][1] += a1*b.y; acc[1][2] += a1*b.z; acc[1][3] += a1*b.w;
    }
    #pragma unroll
    for (int r = 0; r < 2; r++) {
        float4 v = make_float4(acc[r][0], acc[r][1], acc[r][2], acc[r][3]);
        if (sig) {
            v.x = 1.f/(1.f + __expf(-v.x));
            v.y = 1.f/(1.f + __expf(-v.y));
            v.z = 1.f/(1.f + __expf(-v.z));
            v.w = 1.f/(1.f + __expf(-v.w));
        }
        *(float4*)&Out[((size_t)rowBase + ty*2 + r)*C + colBase + tx*4] = v;
    }
}

// ---------------------------------------------------------------------------
// Attention: one block (256 thr) per (b,h). K,V staged in smem (padded).
// Each warp handles 4 q-rows at a time; q broadcast via shfl gives 4x reuse
// of every K smem read. Softmax in registers; probs staged [k][4] for
// float4-broadcast in the PV phase.
// ---------------------------------------------------------------------------
__global__ void attn_kernel(const int* __restrict__ mask) {
    extern __shared__ float sm[];
    float* Ksh = sm;                         // [384][33]
    float* Vsh = Ksh + N*KV_STRIDE;          // [384][33]
    float* Psh = Vsh + N*KV_STRIDE;          // 8 warps x [384][4]
    int b = blockIdx.x, h = blockIdx.y;
    int tid = threadIdx.x, warp = tid >> 5, lane = tid & 31;

    const float* Kg = g_k + (size_t)b*N*C + h*DH;
    const float* Vg = g_v + (size_t)b*N*C + h*DH;
    for (int i = tid; i < N*DH; i += 256) {
        int r = i >> 5, d = i & 31;
        Ksh[r*KV_STRIDE + d] = Kg[(size_t)r*C + d];
        Vsh[r*KV_STRIDE + d] = Vg[(size_t)r*C + d];
    }
    __syncthreads();

    bool mk[12];
    const int* mrow = mask + b*N;
    #pragma unroll
    for (int i = 0; i < 12; i++) mk[i] = mrow[lane + 32*i] > 0;

    float* Pw = Psh + warp * (N*4);
    const float* biasH = g_bias + (size_t)h*NN;
    const float scale = 0.17677669529663687f;   // 1/sqrt(32)

    for (int grp = warp; grp < 96; grp += 8) {
        int q0 = grp * 4;
        float qreg[4];
        #pragma unroll
        for (int r = 0; r < 4; r++)
            qreg[r] = g_q[((size_t)b*N + q0 + r)*C + h*DH + lane];

        float acc[4][12];
        #pragma unroll
        for (int r = 0; r < 4; r++)
            #pragma unroll
            for (int i = 0; i < 12; i++) acc[r][i] = 0.f;

        #pragma unroll 4
        for (int d = 0; d < DH; d++) {
            float q0d = __shfl_sync(0xffffffffu, qreg[0], d);
            float q1d = __shfl_sync(0xffffffffu, qreg[1], d);
            float q2d = __shfl_sync(0xffffffffu, qreg[2], d);
            float q3d = __shfl_sync(0xffffffffu, qreg[3], d);
            #pragma unroll
            for (int i = 0; i < 12; i++) {
                float kv = Ksh[(lane + 32*i)*KV_STRIDE + d];
                acc[0][i] += q0d*kv;
                acc[1][i] += q1d*kv;
                acc[2][i] += q2d*kv;
                acc[3][i] += q3d*kv;
            }
        }

        __syncwarp();
        #pragma unroll
        for (int r = 0; r < 4; r++) {
            const float* brow = biasH + (size_t)(q0 + r)*N;
            float m = -3.0e38f;
            #pragma unroll
            for (int i = 0; i < 12; i++) {
                float v = mk[i] ? (acc[r][i]*scale + brow[lane + 32*i]) : -1e9f;
                acc[r][i] = v;
                m = fmaxf(m, v);
            }
            #pragma unroll
            for (int o = 16; o; o >>= 1) m = fmaxf(m, __shfl_xor_sync(0xffffffffu, m, o));
            float s = 0.f;
            #pragma unroll
            for (int i = 0; i < 12; i++) { float e = __expf(acc[r][i] - m); acc[r][i] = e; s += e; }
            #pragma unroll
            for (int o = 16; o; o >>= 1) s += __shfl_xor_sync(0xffffffffu, s, o);
            float inv = 1.f / s;
            #pragma unroll
            for (int i = 0; i < 12; i++) Pw[(lane + 32*i)*4 + r] = acc[r][i] * inv;
        }
        __syncwarp();

        float o0 = 0, o1 = 0, o2 = 0, o3 = 0;
        #pragma unroll 4
        for (int k = 0; k < N; k++) {
            float v = Vsh[k*KV_STRIDE + lane];
            float4 p = *(const float4*)&Pw[k*4];
            o0 += p.x*v; o1 += p.y*v; o2 += p.z*v; o3 += p.w*v;
        }
        float* Og = g_o + ((size_t)b*N + q0)*C + h*DH + lane;
        Og[0] = o0; Og[C] = o1; Og[2*C] = o2; Og[3*C] = o3;
        __syncwarp();
    }
}

// ---------------------------------------------------------------------------
extern "C" void kernel_launch(void* const* d_in, const int* in_sizes, int n_in,
                              void* d_out, int out_size) {
    const float* pair   = (const float*)d_in[0];
    const int*   mask   = (const int*)  d_in[1];
    const float* ln_w   = (const float*)d_in[2];
    const float* ln_b   = (const float*)d_in[3];
    const float* w_bias = (const float*)d_in[4];
    const float* wq     = (const float*)d_in[5];
    const float* wk     = (const float*)d_in[6];
    const float* wv     = (const float*)d_in[7];
    const float* wg     = (const float*)d_in[8];
    const float* wo     = (const float*)d_in[9];

    float *gx, *gq, *gk, *gv, *gg, *go;
    cudaGetSymbolAddress((void**)&gx, g_x);
    cudaGetSymbolAddress((void**)&gq, g_q);
    cudaGetSymbolAddress((void**)&gk, g_k);
    cudaGetSymbolAddress((void**)&gv, g_v);
    cudaGetSymbolAddress((void**)&gg, g_g);
    cudaGetSymbolAddress((void**)&go, g_o);

    size_t attn_smem = (size_t)(2*N*KV_STRIDE + 8*N*4) * sizeof(float);  // 150528 B
    cudaFuncSetAttribute(attn_kernel, cudaFuncAttributeMaxDynamicSharedMemorySize,
                         (int)attn_smem);

    ln_bias_kernel<<<NN/8, 256>>>(pair, ln_w, ln_b, w_bias);

    dim3 ggrid(NN/32, 2);
    gemm128_kernel<<<ggrid, 256>>>(gx, nullptr, wq, gq, 0);
    gemm128_kernel<<<ggrid, 256>>>(gx, nullptr, wk, gk, 0);
    gemm128_kernel<<<ggrid, 256>>>(gx, nullptr, wv, gv, 0);
    gemm128_kernel<<<ggrid, 256>>>(gx, nullptr, wg, gg, 1);

    attn_kernel<<<dim3(N, H), 256, attn_smem>>>(mask);

    gemm128_kernel<<<ggrid, 256>>>(go, gg, wo, (float*)d_out, 0);
}

// round 2
// speedup vs baseline: 1.0298x; 1.0298x over previous
#include <cuda_runtime.h>
#include <math.h>

#define N   384
#define C   128
#define H   4
#define DH  32
#define NN  (N*N)
#define KV_STRIDE 33

// Scratch (allocation-free rule: __device__ globals)
__device__ float g_x[NN*C];
__device__ float g_q[NN*C];
__device__ float g_k[NN*C];
__device__ float g_v[NN*C];
__device__ float g_g[NN*C];
__device__ float g_o[NN*C];
__device__ float g_bias[H*NN];

// ---------------------------------------------------------------------------
// LayerNorm over C + per-head pair bias. One warp per (q,k) row.
// ---------------------------------------------------------------------------
__global__ void ln_bias_kernel(const float* __restrict__ pair,
                               const float* __restrict__ ln_w,
                               const float* __restrict__ ln_b,
                               const float* __restrict__ w_bias) {
    int warp = threadIdx.x >> 5, lane = threadIdx.x & 31;
    int row = blockIdx.x * 8 + warp;             // row = q*N + k
    const float* p = pair + (size_t)row * C;
    float x0 = p[lane], x1 = p[lane+32], x2 = p[lane+64], x3 = p[lane+96];
    float s = x0 + x1 + x2 + x3;
    #pragma unroll
    for (int o = 16; o; o >>= 1) s += __shfl_xor_sync(0xffffffffu, s, o);
    float mu = s * (1.0f / C);
    float d0 = x0-mu, d1 = x1-mu, d2 = x2-mu, d3 = x3-mu;
    float s2 = d0*d0 + d1*d1 + d2*d2 + d3*d3;
    #pragma unroll
    for (int o = 16; o; o >>= 1) s2 += __shfl_xor_sync(0xffffffffu, s2, o);
    float rstd = rsqrtf(s2 * (1.0f / C) + 1e-5f);
    x0 = d0*rstd*ln_w[lane]    + ln_b[lane];
    x1 = d1*rstd*ln_w[lane+32] + ln_b[lane+32];
    x2 = d2*rstd*ln_w[lane+64] + ln_b[lane+64];
    x3 = d3*rstd*ln_w[lane+96] + ln_b[lane+96];
    float* xo = g_x + (size_t)row * C;
    xo[lane] = x0; xo[lane+32] = x1; xo[lane+64] = x2; xo[lane+96] = x3;
    #pragma unroll
    for (int h = 0; h < H; h++) {
        float bs = x0*w_bias[lane*H + h]      + x1*w_bias[(lane+32)*H + h]
                 + x2*w_bias[(lane+64)*H + h] + x3*w_bias[(lane+96)*H + h];
        #pragma unroll
        for (int o = 16; o; o >>= 1) bs += __shfl_xor_sync(0xffffffffu, bs, o);
        if (lane == 0) g_bias[h*NN + row] = bs;
    }
}

// ---------------------------------------------------------------------------
// Fused multi-weight SGEMM: A[64-row tile] staged once in smem, then loop over
// (weight, col-half) tiles. 4x4 register tile, k-chunks of 4 with float4 loads
// of both operands: 8 LDS.128 + 64 FMA per chunk.
// ---------------------------------------------------------------------------
__global__ __launch_bounds__(256) void gemm_fused_kernel(
    const float* __restrict__ A, const float* __restrict__ A2,
    const float* __restrict__ W0, const float* __restrict__ W1,
    const float* __restrict__ W2, const float* __restrict__ W3,
    float* __restrict__ O0, float* __restrict__ O1,
    float* __restrict__ O2, float* __restrict__ O3,
    int nit, int sigmask)
{
    extern __shared__ float sm[];
    float* As = sm;            // [64][128]
    float* Ws = sm + 64*128;   // [128][64]
    const float* Wlist[4] = {W0, W1, W2, W3};
    float*       Olist[4] = {O0, O1, O2, O3};

    int rowBase = blockIdx.x * 64;
    int tid = threadIdx.x;
    const float* Ap = A + (size_t)rowBase * C;
    if (A2) {
        const float* A2p = A2 + (size_t)rowBase * C;
        #pragma unroll
        for (int i = tid; i < 64*128; i += 256) As[i] = Ap[i] * A2p[i];
    } else {
        #pragma unroll
        for (int i = tid; i < 64*128; i += 256) As[i] = Ap[i];
    }

    int tx = tid & 15, ty = tid >> 4;   // tx: col group, ty: row group

    for (int it = 0; it < nit; it++) {
        int w = it >> 1;
        int colBase = (it & 1) * 64;
        const float* W = Wlist[w];
        __syncthreads();   // As ready (it=0) / prior compute done reading Ws
        #pragma unroll
        for (int i = tid; i < 128*64; i += 256)
            Ws[i] = W[(i >> 6) * C + colBase + (i & 63)];
        __syncthreads();

        float acc[4][4];
        #pragma unroll
        for (int r = 0; r < 4; r++)
            #pragma unroll
            for (int c = 0; c < 4; c++) acc[r][c] = 0.f;

        #pragma unroll 2
        for (int k0 = 0; k0 < 128; k0 += 4) {
            float av[4][4], bv[4][4];
            #pragma unroll
            for (int r = 0; r < 4; r++)
                *(float4*)av[r] = *(const float4*)&As[(ty*4 + r)*128 + k0];
            #pragma unroll
            for (int kk = 0; kk < 4; kk++)
                *(float4*)bv[kk] = *(const float4*)&Ws[(k0 + kk)*64 + tx*4];
            #pragma unroll
            for (int r = 0; r < 4; r++)
                #pragma unroll
                for (int c = 0; c < 4; c++)
                    acc[r][c] += av[r][0]*bv[0][c] + av[r][1]*bv[1][c]
                               + av[r][2]*bv[2][c] + av[r][3]*bv[3][c];
        }

        int sig = (sigmask >> w) & 1;
        float* O = Olist[w];
        #pragma unroll
        for (int r = 0; r < 4; r++) {
            float4 v = make_float4(acc[r][0], acc[r][1], acc[r][2], acc[r][3]);
            if (sig) {
                v.x = 1.f/(1.f + __expf(-v.x));
                v.y = 1.f/(1.f + __expf(-v.y));
                v.z = 1.f/(1.f + __expf(-v.z));
                v.w = 1.f/(1.f + __expf(-v.w));
            }
            *(float4*)&O[((size_t)rowBase + ty*4 + r)*C + colBase + tx*4] = v;
        }
    }
}

// ---------------------------------------------------------------------------
// Attention: one block (256 thr) per (b,h). K,V staged in smem (padded).
// Each warp processes 8 q-rows per group: two 4-row QK/softmax passes fill
// Pw[384][8], then one 8-row PV pass (3 LDS per 8 FMA).
// ---------------------------------------------------------------------------
__global__ __launch_bounds__(256) void attn_kernel(const int* __restrict__ mask) {
    extern __shared__ float sm[];
    float* Ksh = sm;                         // [384][33]
    float* Vsh = Ksh + N*KV_STRIDE;          // [384][33]
    float* Psh = Vsh + N*KV_STRIDE;          // 8 warps x [384][8]
    int b = blockIdx.x, h = blockIdx.y;
    int tid = threadIdx.x, warp = tid >> 5, lane = tid & 31;

    const float* Kg = g_k + (size_t)b*N*C + h*DH;
    const float* Vg = g_v + (size_t)b*N*C + h*DH;
    for (int i = tid; i < N*DH; i += 256) {
        int r = i >> 5, d = i & 31;
        Ksh[r*KV_STRIDE + d] = Kg[(size_t)r*C + d];
        Vsh[r*KV_STRIDE + d] = Vg[(size_t)r*C + d];
    }
    __syncthreads();

    bool mk[12];
    const int* mrow = mask + b*N;
    #pragma unroll
    for (int i = 0; i < 12; i++) mk[i] = mrow[lane + 32*i] > 0;

    float* Pw = Psh + warp * (N*8);
    const float* biasH = g_bias + (size_t)h*NN;
    const float scale = 0.17677669529663687f;   // 1/sqrt(32)

    for (int grp = warp; grp < 48; grp += 8) {
        int q0 = grp * 8;

        #pragma unroll
        for (int half = 0; half < 2; half++) {
            int qh = q0 + half*4;
            float qreg[4];
            #pragma unroll
            for (int r = 0; r < 4; r++)
                qreg[r] = g_q[((size_t)b*N + qh + r)*C + h*DH + lane];

            float acc[4][12];
            #pragma unroll
            for (int r = 0; r < 4; r++)
                #pragma unroll
                for (int i = 0; i < 12; i++) acc[r][i] = 0.f;

            #pragma unroll 4
            for (int d = 0; d < DH; d++) {
                float q0d = __shfl_sync(0xffffffffu, qreg[0], d);
                float q1d = __shfl_sync(0xffffffffu, qreg[1], d);
                float q2d = __shfl_sync(0xffffffffu, qreg[2], d);
                float q3d = __shfl_sync(0xffffffffu, qreg[3], d);
                #pragma unroll
                for (int i = 0; i < 12; i++) {
                    float kv = Ksh[(lane + 32*i)*KV_STRIDE + d];
                    acc[0][i] += q0d*kv;
                    acc[1][i] += q1d*kv;
                    acc[2][i] += q2d*kv;
                    acc[3][i] += q3d*kv;
                }
            }

            #pragma unroll
            for (int r = 0; r < 4; r++) {
                const float* brow = biasH + (size_t)(qh + r)*N;
                float m = -3.0e38f;
                #pragma unroll
                for (int i = 0; i < 12; i++) {
                    float v = mk[i] ? (acc[r][i]*scale + brow[lane + 32*i]) : -1e9f;
                    acc[r][i] = v;
                    m = fmaxf(m, v);
                }
                #pragma unroll
                for (int o = 16; o; o >>= 1) m = fmaxf(m, __shfl_xor_sync(0xffffffffu, m, o));
                float s = 0.f;
                #pragma unroll
                for (int i = 0; i < 12; i++) { float e = __expf(acc[r][i] - m); acc[r][i] = e; s += e; }
                #pragma unroll
                for (int o = 16; o; o >>= 1) s += __shfl_xor_sync(0xffffffffu, s, o);
                float inv = 1.f / s;
                #pragma unroll
                for (int i = 0; i < 12; i++) Pw[(lane + 32*i)*8 + half*4 + r] = acc[r][i] * inv;
            }
        }
        __syncwarp();

        float o[8];
        #pragma unroll
        for (int r = 0; r < 8; r++) o[r] = 0.f;
        #pragma unroll 4
        for (int k = 0; k < N; k++) {
            float v = Vsh[k*KV_STRIDE + lane];
            float4 p0 = *(const float4*)&Pw[k*8];
            float4 p1 = *(const float4*)&Pw[k*8 + 4];
            o[0] += p0.x*v; o[1] += p0.y*v; o[2] += p0.z*v; o[3] += p0.w*v;
            o[4] += p1.x*v; o[5] += p1.y*v; o[6] += p1.z*v; o[7] += p1.w*v;
        }
        float* Og = g_o + ((size_t)b*N + q0)*C + h*DH + lane;
        #pragma unroll
        for (int r = 0; r < 8; r++) Og[r*C] = o[r];
        __syncwarp();
    }
}

// ---------------------------------------------------------------------------
extern "C" void kernel_launch(void* const* d_in, const int* in_sizes, int n_in,
                              void* d_out, int out_size) {
    const float* pair   = (const float*)d_in[0];
    const int*   mask   = (const int*)  d_in[1];
    const float* ln_w   = (const float*)d_in[2];
    const float* ln_b   = (const float*)d_in[3];
    const float* w_bias = (const float*)d_in[4];
    const float* wq     = (const float*)d_in[5];
    const float* wk     = (const float*)d_in[6];
    const float* wv     = (const float*)d_in[7];
    const float* wg     = (const float*)d_in[8];
    const float* wo     = (const float*)d_in[9];

    float *gx, *gq, *gk, *gv, *gg, *go;
    cudaGetSymbolAddress((void**)&gx, g_x);
    cudaGetSymbolAddress((void**)&gq, g_q);
    cudaGetSymbolAddress((void**)&gk, g_k);
    cudaGetSymbolAddress((void**)&gv, g_v);
    cudaGetSymbolAddress((void**)&gg, g_g);
    cudaGetSymbolAddress((void**)&go, g_o);

    size_t gemm_smem = (size_t)(64*128 + 128*64) * sizeof(float);          // 64 KB
    size_t attn_smem = (size_t)(2*N*KV_STRIDE + 8*N*8) * sizeof(float);    // ~195 KB
    cudaFuncSetAttribute(gemm_fused_kernel, cudaFuncAttributeMaxDynamicSharedMemorySize,
                         (int)gemm_smem);
    cudaFuncSetAttribute(attn_kernel, cudaFuncAttributeMaxDynamicSharedMemorySize,
                         (int)attn_smem);

    ln_bias_kernel<<<NN/8, 256>>>(pair, ln_w, ln_b, w_bias);

    // Fused Q/K/V/Gate projections (gate gets sigmoid: w index 3 -> bit 3)
    gemm_fused_kernel<<<NN/64, 256, gemm_smem>>>(
        gx, nullptr, wq, wk, wv, wg, gq, gk, gv, gg, 8, 8);

    attn_kernel<<<dim3(N, H), 256, attn_smem>>>(mask);

    // Output projection: (o * gate) @ wo
    gemm_fused_kernel<<<NN/64, 256, gemm_smem>>>(
        go, gg, wo, nullptr, nullptr, nullptr, (float*)d_out, nullptr, nullptr, nullptr, 2, 0);
}

// round 3
// speedup vs baseline: 1.3382x; 1.2995x over previous
#include <cuda_runtime.h>
#include <math.h>

#define N   384
#define C   128
#define H   4
#define DH  32
#define NN  (N*N)
#define KV_STRIDE 33

// Scratch (allocation-free rule: __device__ globals)
__device__ float g_x[NN*C];
__device__ float g_q[NN*C];
__device__ float g_k[NN*C];
__device__ float g_v[NN*C];
__device__ float g_g[NN*C];
__device__ float g_o[NN*C];
__device__ float g_bias[H*NN];

// ---------------------------------------------------------------------------
// LayerNorm over C + per-head pair bias. One warp per (q,k) row.
// ---------------------------------------------------------------------------
__global__ void ln_bias_kernel(const float* __restrict__ pair,
                               const float* __restrict__ ln_w,
                               const float* __restrict__ ln_b,
                               const float* __restrict__ w_bias) {
    int warp = threadIdx.x >> 5, lane = threadIdx.x & 31;
    int row = blockIdx.x * 8 + warp;             // row = q*N + k
    const float* p = pair + (size_t)row * C;
    float x0 = p[lane], x1 = p[lane+32], x2 = p[lane+64], x3 = p[lane+96];
    float s = x0 + x1 + x2 + x3;
    #pragma unroll
    for (int o = 16; o; o >>= 1) s += __shfl_xor_sync(0xffffffffu, s, o);
    float mu = s * (1.0f / C);
    float d0 = x0-mu, d1 = x1-mu, d2 = x2-mu, d3 = x3-mu;
    float s2 = d0*d0 + d1*d1 + d2*d2 + d3*d3;
    #pragma unroll
    for (int o = 16; o; o >>= 1) s2 += __shfl_xor_sync(0xffffffffu, s2, o);
    float rstd = rsqrtf(s2 * (1.0f / C) + 1e-5f);
    x0 = d0*rstd*ln_w[lane]    + ln_b[lane];
    x1 = d1*rstd*ln_w[lane+32] + ln_b[lane+32];
    x2 = d2*rstd*ln_w[lane+64] + ln_b[lane+64];
    x3 = d3*rstd*ln_w[lane+96] + ln_b[lane+96];
    float* xo = g_x + (size_t)row * C;
    xo[lane] = x0; xo[lane+32] = x1; xo[lane+64] = x2; xo[lane+96] = x3;
    #pragma unroll
    for (int h = 0; h < H; h++) {
        float bs = x0*w_bias[lane*H + h]      + x1*w_bias[(lane+32)*H + h]
                 + x2*w_bias[(lane+64)*H + h] + x3*w_bias[(lane+96)*H + h];
        #pragma unroll
        for (int o = 16; o; o >>= 1) bs += __shfl_xor_sync(0xffffffffu, bs, o);
        if (lane == 0) g_bias[h*NN + row] = bs;
    }
}

// ---------------------------------------------------------------------------
// Fused multi-weight SGEMM. Block tile 128 rows x 64 cols, 8x4 register tile.
// A staged once per block; loop over (weight, col-half) tiles streams W.
// Per k-chunk of 4: 12 LDS.128 + 128 FMA per thread -> FMA-bound.
// ---------------------------------------------------------------------------
__global__ __launch_bounds__(256) void gemm_fused_kernel(
    const float* __restrict__ A, const float* __restrict__ A2,
    const float* __restrict__ W0, const float* __restrict__ W1,
    const float* __restrict__ W2, const float* __restrict__ W3,
    float* __restrict__ O0, float* __restrict__ O1,
    float* __restrict__ O2, float* __restrict__ O3,
    int nit, int sigmask)
{
    extern __shared__ float sm[];
    float* As = sm;             // [128][128]
    float* Ws = sm + 128*128;   // [128][64]
    const float* Wlist[4] = {W0, W1, W2, W3};
    float*       Olist[4] = {O0, O1, O2, O3};

    int rowBase = blockIdx.x * 128;
    int tid = threadIdx.x;
    const float* Ap = A + (size_t)rowBase * C;
    if (A2) {
        const float* A2p = A2 + (size_t)rowBase * C;
        #pragma unroll
        for (int i = tid*4; i < 128*128; i += 1024) {
            float4 a = *(const float4*)&Ap[i];
            float4 b = *(const float4*)&A2p[i];
            a.x *= b.x; a.y *= b.y; a.z *= b.z; a.w *= b.w;
            *(float4*)&As[i] = a;
        }
    } else {
        #pragma unroll
        for (int i = tid*4; i < 128*128; i += 1024)
            *(float4*)&As[i] = *(const float4*)&Ap[i];
    }

    int tx = tid & 15, ty = tid >> 4;   // tx: col group (x4), ty: row group (x8)

    for (int it = 0; it < nit; it++) {
        int w = it >> 1;
        int colBase = (it & 1) * 64;
        const float* W = Wlist[w];
        __syncthreads();   // As ready (it=0) / prior compute done reading Ws
        #pragma unroll
        for (int i = tid*4; i < 128*64; i += 1024) {
            int kr = i >> 6, kc = i & 63;
            *(float4*)&Ws[i] = *(const float4*)&W[kr * C + colBase + kc];
        }
        __syncthreads();

        float acc[8][4];
        #pragma unroll
        for (int r = 0; r < 8; r++)
            #pragma unroll
            for (int c = 0; c < 4; c++) acc[r][c] = 0.f;

        for (int k0 = 0; k0 < 128; k0 += 4) {
            float av[8][4], bv[4][4];
            #pragma unroll
            for (int kk = 0; kk < 4; kk++)
                *(float4*)bv[kk] = *(const float4*)&Ws[(k0 + kk)*64 + tx*4];
            #pragma unroll
            for (int r = 0; r < 8; r++)
                *(float4*)av[r] = *(const float4*)&As[(ty*8 + r)*128 + k0];
            #pragma unroll
            for (int r = 0; r < 8; r++)
                #pragma unroll
                for (int c = 0; c < 4; c++)
                    acc[r][c] += av[r][0]*bv[0][c] + av[r][1]*bv[1][c]
                               + av[r][2]*bv[2][c] + av[r][3]*bv[3][c];
        }

        int sig = (sigmask >> w) & 1;
        float* O = Olist[w];
        #pragma unroll
        for (int r = 0; r < 8; r++) {
            float4 v = make_float4(acc[r][0], acc[r][1], acc[r][2], acc[r][3]);
            if (sig) {
                v.x = 1.f/(1.f + __expf(-v.x));
                v.y = 1.f/(1.f + __expf(-v.y));
                v.z = 1.f/(1.f + __expf(-v.z));
                v.w = 1.f/(1.f + __expf(-v.w));
            }
            *(float4*)&O[((size_t)rowBase + ty*8 + r)*C + colBase + tx*4] = v;
        }
    }
}

// ---------------------------------------------------------------------------
// Attention: one block (512 thr, 16 warps) per (b,h). K,V staged in smem.
// Each warp handles 4 q-rows per group. Probs stored PLANAR per warp:
// Psh[warp][r][384] -> conflict-free STS; PV reads broadcast float4 over k.
// ---------------------------------------------------------------------------
__global__ __launch_bounds__(512) void attn_kernel(const int* __restrict__ mask) {
    extern __shared__ float sm[];
    float* Ksh = sm;                         // [384][33]
    float* Vsh = Ksh + N*KV_STRIDE;          // [384][33]
    float* Psh = Vsh + N*KV_STRIDE;          // 16 warps x [4][384]
    int b = blockIdx.x, h = blockIdx.y;
    int tid = threadIdx.x, warp = tid >> 5, lane = tid & 31;

    const float* Kg = g_k + (size_t)b*N*C + h*DH;
    const float* Vg = g_v + (size_t)b*N*C + h*DH;
    for (int i = tid; i < N*DH; i += 512) {
        int r = i >> 5, d = i & 31;
        Ksh[r*KV_STRIDE + d] = Kg[(size_t)r*C + d];
        Vsh[r*KV_STRIDE + d] = Vg[(size_t)r*C + d];
    }
    __syncthreads();

    bool mk[12];
    const int* mrow = mask + b*N;
    #pragma unroll
    for (int i = 0; i < 12; i++) mk[i] = mrow[lane + 32*i] > 0;

    float* Pw = Psh + warp * (4*N);
    const float* biasH = g_bias + (size_t)h*NN;
    const float scale = 0.17677669529663687f;   // 1/sqrt(32)

    for (int grp = warp; grp < 96; grp += 16) {
        int q0 = grp * 4;
        float qreg[4];
        #pragma unroll
        for (int r = 0; r < 4; r++)
            qreg[r] = g_q[((size_t)b*N + q0 + r)*C + h*DH + lane];

        float acc[4][12];
        #pragma unroll
        for (int r = 0; r < 4; r++)
            #pragma unroll
            for (int i = 0; i < 12; i++) acc[r][i] = 0.f;

        #pragma unroll 4
        for (int d = 0; d < DH; d++) {
            float q0d = __shfl_sync(0xffffffffu, qreg[0], d);
            float q1d = __shfl_sync(0xffffffffu, qreg[1], d);
            float q2d = __shfl_sync(0xffffffffu, qreg[2], d);
            float q3d = __shfl_sync(0xffffffffu, qreg[3], d);
            #pragma unroll
            for (int i = 0; i < 12; i++) {
                float kv = Ksh[(lane + 32*i)*KV_STRIDE + d];
                acc[0][i] += q0d*kv;
                acc[1][i] += q1d*kv;
                acc[2][i] += q2d*kv;
                acc[3][i] += q3d*kv;
            }
        }

        #pragma unroll
        for (int r = 0; r < 4; r++) {
            const float* brow = biasH + (size_t)(q0 + r)*N;
            float m = -3.0e38f;
            #pragma unroll
            for (int i = 0; i < 12; i++) {
                float v = mk[i] ? (acc[r][i]*scale + brow[lane + 32*i]) : -1e9f;
                acc[r][i] = v;
                m = fmaxf(m, v);
            }
            #pragma unroll
            for (int o = 16; o; o >>= 1) m = fmaxf(m, __shfl_xor_sync(0xffffffffu, m, o));
            float s = 0.f;
            #pragma unroll
            for (int i = 0; i < 12; i++) { float e = __expf(acc[r][i] - m); acc[r][i] = e; s += e; }
            #pragma unroll
            for (int o = 16; o; o >>= 1) s += __shfl_xor_sync(0xffffffffu, s, o);
            float inv = 1.f / s;
            // planar, conflict-free store
            #pragma unroll
            for (int i = 0; i < 12; i++) Pw[r*N + lane + 32*i] = acc[r][i] * inv;
        }
        __syncwarp();

        float o0 = 0, o1 = 0, o2 = 0, o3 = 0;
        #pragma unroll 2
        for (int k0 = 0; k0 < N; k0 += 4) {
            float4 p0 = *(const float4*)&Pw[0*N + k0];
            float4 p1 = *(const float4*)&Pw[1*N + k0];
            float4 p2 = *(const float4*)&Pw[2*N + k0];
            float4 p3 = *(const float4*)&Pw[3*N + k0];
            float va = Vsh[(k0+0)*KV_STRIDE + lane];
            float vb = Vsh[(k0+1)*KV_STRIDE + lane];
            float vc = Vsh[(k0+2)*KV_STRIDE + lane];
            float vd = Vsh[(k0+3)*KV_STRIDE + lane];
            o0 += p0.x*va + p0.y*vb + p0.z*vc + p0.w*vd;
            o1 += p1.x*va + p1.y*vb + p1.z*vc + p1.w*vd;
            o2 += p2.x*va + p2.y*vb + p2.z*vc + p2.w*vd;
            o3 += p3.x*va + p3.y*vb + p3.z*vc + p3.w*vd;
        }
        float* Og = g_o + ((size_t)b*N + q0)*C + h*DH + lane;
        Og[0] = o0; Og[C] = o1; Og[2*C] = o2; Og[3*C] = o3;
        __syncwarp();
    }
}

// ---------------------------------------------------------------------------
extern "C" void kernel_launch(void* const* d_in, const int* in_sizes, int n_in,
                              void* d_out, int out_size) {
    const float* pair   = (const float*)d_in[0];
    const int*   mask   = (const int*)  d_in[1];
    const float* ln_w   = (const float*)d_in[2];
    const float* ln_b   = (const float*)d_in[3];
    const float* w_bias = (const float*)d_in[4];
    const float* wq     = (const float*)d_in[5];
    const float* wk     = (const float*)d_in[6];
    const float* wv     = (const float*)d_in[7];
    const float* wg     = (const float*)d_in[8];
    const float* wo     = (const float*)d_in[9];

    float *gx, *gq, *gk, *gv, *gg, *go;
    cudaGetSymbolAddress((void**)&gx, g_x);
    cudaGetSymbolAddress((void**)&gq, g_q);
    cudaGetSymbolAddress((void**)&gk, g_k);
    cudaGetSymbolAddress((void**)&gv, g_v);
    cudaGetSymbolAddress((void**)&gg, g_g);
    cudaGetSymbolAddress((void**)&go, g_o);

    size_t gemm_smem = (size_t)(128*128 + 128*64) * sizeof(float);         // 96 KB
    size_t attn_smem = (size_t)(2*N*KV_STRIDE + 16*4*N) * sizeof(float);   // ~195 KB
    cudaFuncSetAttribute(gemm_fused_kernel, cudaFuncAttributeMaxDynamicSharedMemorySize,
                         (int)gemm_smem);
    cudaFuncSetAttribute(attn_kernel, cudaFuncAttributeMaxDynamicSharedMemorySize,
                         (int)attn_smem);

    ln_bias_kernel<<<NN/8, 256>>>(pair, ln_w, ln_b, w_bias);

    // Fused Q/K/V/Gate projections (gate gets sigmoid: w index 3 -> bit 3)
    gemm_fused_kernel<<<NN/128, 256, gemm_smem>>>(
        gx, nullptr, wq, wk, wv, wg, gq, gk, gv, gg, 8, 8);

    attn_kernel<<<dim3(N, H), 512, attn_smem>>>(mask);

    // Output projection: (o * gate) @ wo
    gemm_fused_kernel<<<NN/128, 256, gemm_smem>>>(
        go, gg, wo, nullptr, nullptr, nullptr, (float*)d_out, nullptr, nullptr, nullptr, 2, 0);
}

// round 4
// speedup vs baseline: 1.4841x; 1.1090x over previous
#include <cuda_runtime.h>
#include <math.h>

#define N   384
#define C   128
#define H   4
#define DH  32
#define NN  (N*N)
#define KS  34          // Ksh row stride (floats, even -> 8B-aligned float2)
#define VS2 33          // Vsh2 row stride in float2 units

typedef unsigned long long ull;

// Scratch (allocation-free rule: __device__ globals)
__device__ float g_x[NN*C];
__device__ float g_q[NN*C];
__device__ float g_k[NN*C];
__device__ float g_v[NN*C];
__device__ float g_g[NN*C];
__device__ float g_o[NN*C];
__device__ float g_bias[H*NN];

// --------------------------- f32x2 helpers ---------------------------------
__device__ __forceinline__ void ffma2(ull& d, ull a, ull b, ull c) {
    asm("fma.rn.f32x2 %0, %1, %2, %3;" : "=l"(d) : "l"(a), "l"(b), "l"(c));
}
__device__ __forceinline__ ull pack_dup(float a) {
    ull r; asm("mov.b64 %0, {%1, %1};" : "=l"(r) : "f"(a)); return r;
}
__device__ __forceinline__ float hsum2(ull a) {
    float lo, hi; asm("mov.b64 {%0, %1}, %2;" : "=f"(lo), "=f"(hi) : "l"(a));
    return lo + hi;
}

// ---------------------------------------------------------------------------
// LayerNorm over C + per-head pair bias. One warp per (q,k) row.
// ---------------------------------------------------------------------------
__global__ void ln_bias_kernel(const float* __restrict__ pair,
                               const float* __restrict__ ln_w,
                               const float* __restrict__ ln_b,
                               const float* __restrict__ w_bias) {
    int warp = threadIdx.x >> 5, lane = threadIdx.x & 31;
    int row = blockIdx.x * 8 + warp;             // row = q*N + k
    const float* p = pair + (size_t)row * C;
    float x0 = p[lane], x1 = p[lane+32], x2 = p[lane+64], x3 = p[lane+96];
    float s = x0 + x1 + x2 + x3;
    #pragma unroll
    for (int o = 16; o; o >>= 1) s += __shfl_xor_sync(0xffffffffu, s, o);
    float mu = s * (1.0f / C);
    float d0 = x0-mu, d1 = x1-mu, d2 = x2-mu, d3 = x3-mu;
    float s2 = d0*d0 + d1*d1 + d2*d2 + d3*d3;
    #pragma unroll
    for (int o = 16; o; o >>= 1) s2 += __shfl_xor_sync(0xffffffffu, s2, o);
    float rstd = rsqrtf(s2 * (1.0f / C) + 1e-5f);
    x0 = d0*rstd*ln_w[lane]    + ln_b[lane];
    x1 = d1*rstd*ln_w[lane+32] + ln_b[lane+32];
    x2 = d2*rstd*ln_w[lane+64] + ln_b[lane+64];
    x3 = d3*rstd*ln_w[lane+96] + ln_b[lane+96];
    float* xo = g_x + (size_t)row * C;
    xo[lane] = x0; xo[lane+32] = x1; xo[lane+64] = x2; xo[lane+96] = x3;
    #pragma unroll
    for (int h = 0; h < H; h++) {
        float bs = x0*w_bias[lane*H + h]      + x1*w_bias[(lane+32)*H + h]
                 + x2*w_bias[(lane+64)*H + h] + x3*w_bias[(lane+96)*H + h];
        #pragma unroll
        for (int o = 16; o; o >>= 1) bs += __shfl_xor_sync(0xffffffffu, bs, o);
        if (lane == 0) g_bias[h*NN + row] = bs;
    }
}

// ---------------------------------------------------------------------------
// Fused multi-weight SGEMM. Block tile 128 rows x 64 cols, 8x4 register tile,
// inner product in packed f32x2 (2 FFMA2 per (r,kk) on adjacent W columns).
// ---------------------------------------------------------------------------
__global__ __launch_bounds__(256) void gemm_fused_kernel(
    const float* __restrict__ A, const float* __restrict__ A2,
    const float* __restrict__ W0, const float* __restrict__ W1,
    const float* __restrict__ W2, const float* __restrict__ W3,
    float* __restrict__ O0, float* __restrict__ O1,
    float* __restrict__ O2, float* __restrict__ O3,
    int nit, int sigmask)
{
    extern __shared__ float sm[];
    float* As = sm;             // [128][128]
    float* Ws = sm + 128*128;   // [128][64]
    const float* Wlist[4] = {W0, W1, W2, W3};
    float*       Olist[4] = {O0, O1, O2, O3};

    int rowBase = blockIdx.x * 128;
    int tid = threadIdx.x;
    const float* Ap = A + (size_t)rowBase * C;
    if (A2) {
        const float* A2p = A2 + (size_t)rowBase * C;
        #pragma unroll
        for (int i = tid*4; i < 128*128; i += 1024) {
            float4 a = *(const float4*)&Ap[i];
            float4 b = *(const float4*)&A2p[i];
            a.x *= b.x; a.y *= b.y; a.z *= b.z; a.w *= b.w;
            *(float4*)&As[i] = a;
        }
    } else {
        #pragma unroll
        for (int i = tid*4; i < 128*128; i += 1024)
            *(float4*)&As[i] = *(const float4*)&Ap[i];
    }

    int tx = tid & 15, ty = tid >> 4;

    for (int it = 0; it < nit; it++) {
        int w = it >> 1;
        int colBase = (it & 1) * 64;
        const float* W = Wlist[w];
        __syncthreads();
        #pragma unroll
        for (int i = tid*4; i < 128*64; i += 1024) {
            int kr = i >> 6, kc = i & 63;
            *(float4*)&Ws[i] = *(const float4*)&W[kr * C + colBase + kc];
        }
        __syncthreads();

        ull acc2[8][2];
        #pragma unroll
        for (int r = 0; r < 8; r++) { acc2[r][0] = 0ull; acc2[r][1] = 0ull; }

        for (int k0 = 0; k0 < 128; k0 += 4) {
            float av[8][4]; ulonglong2 bv[4];
            #pragma unroll
            for (int kk = 0; kk < 4; kk++)
                bv[kk] = *(const ulonglong2*)&Ws[(k0 + kk)*64 + tx*4];
            #pragma unroll
            for (int r = 0; r < 8; r++)
                *(float4*)av[r] = *(const float4*)&As[(ty*8 + r)*128 + k0];
            #pragma unroll
            for (int r = 0; r < 8; r++)
                #pragma unroll
                for (int kk = 0; kk < 4; kk++) {
                    ull a2 = pack_dup(av[r][kk]);
                    ffma2(acc2[r][0], a2, bv[kk].x, acc2[r][0]);
                    ffma2(acc2[r][1], a2, bv[kk].y, acc2[r][1]);
                }
        }

        int sig = (sigmask >> w) & 1;
        float* O = Olist[w];
        #pragma unroll
        for (int r = 0; r < 8; r++) {
            float lo0, hi0, lo1, hi1;
            asm("mov.b64 {%0, %1}, %2;" : "=f"(lo0), "=f"(hi0) : "l"(acc2[r][0]));
            asm("mov.b64 {%0, %1}, %2;" : "=f"(lo1), "=f"(hi1) : "l"(acc2[r][1]));
            float4 v = make_float4(lo0, hi0, lo1, hi1);
            if (sig) {
                v.x = 1.f/(1.f + __expf(-v.x));
                v.y = 1.f/(1.f + __expf(-v.y));
                v.z = 1.f/(1.f + __expf(-v.z));
                v.w = 1.f/(1.f + __expf(-v.w));
            }
            *(float4*)&O[((size_t)rowBase + ty*8 + r)*C + colBase + tx*4] = v;
        }
    }
}

// ---------------------------------------------------------------------------
// Attention: one block (512 thr) per (b,h). All hot math in packed f32x2.
// QK: pair over d (even/odd partial sums); two passes over 6 k-columns each
// (raw logits staged in planar Pw). PV: pair over k with pre-packed V.
// ---------------------------------------------------------------------------
__global__ __launch_bounds__(512) void attn_kernel(const int* __restrict__ mask) {
    extern __shared__ float sm[];
    float* Ksh   = sm;                        // [384][34]
    float* Vsh2f = Ksh + N*KS;                // 192 x [VS2 float2]  (packed k-pairs)
    float* Psh   = Vsh2f + 192*VS2*2;         // 16 warps x [4][384]
    float* Qsh   = Psh + 16*4*N;              // 16 warps x [4][32]
    int b = blockIdx.x, h = blockIdx.y;
    int tid = threadIdx.x, warp = tid >> 5, lane = tid & 31;

    const float* Kg = g_k + (size_t)b*N*C + h*DH;
    const float* Vg = g_v + (size_t)b*N*C + h*DH;
    for (int i = tid; i < N*DH; i += 512) {
        int r = i >> 5, d = i & 31;
        Ksh[r*KS + d] = Kg[(size_t)r*C + d];
        // pack V k-pairs: Vsh2[k>>1][d] = {V[k_even][d], V[k_odd][d]}
        Vsh2f[(r >> 1)*(VS2*2) + d*2 + (r & 1)] = Vg[(size_t)r*C + d];
    }
    __syncthreads();

    bool mk[12];
    const int* mrow = mask + b*N;
    #pragma unroll
    for (int i = 0; i < 12; i++) mk[i] = mrow[lane + 32*i] > 0;

    float* Pw = Psh + warp * (4*N);
    float* Qw = Qsh + warp * 128;
    const ull* V2 = (const ull*)Vsh2f;
    const float* biasH = g_bias + (size_t)h*NN;
    const float scale = 0.17677669529663687f;   // 1/sqrt(32)

    for (int grp = warp; grp < 96; grp += 16) {
        int q0 = grp * 4;
        #pragma unroll
        for (int r = 0; r < 4; r++)
            Qw[r*32 + lane] = g_q[((size_t)b*N + q0 + r)*C + h*DH + lane];
        __syncwarp();

        // ---- QK: two passes of 6 k-columns, acc paired over d ----
        #pragma unroll
        for (int pass = 0; pass < 2; pass++) {
            ull acc2[4][6];
            #pragma unroll
            for (int r = 0; r < 4; r++)
                #pragma unroll
                for (int ii = 0; ii < 6; ii++) acc2[r][ii] = 0ull;

            #pragma unroll 4
            for (int dp = 0; dp < 16; dp++) {
                ull q2[4];
                #pragma unroll
                for (int r = 0; r < 4; r++)
                    q2[r] = *(const ull*)&Qw[r*32 + 2*dp];
                #pragma unroll
                for (int ii = 0; ii < 6; ii++) {
                    int i = pass*6 + ii;
                    ull k2 = *(const ull*)&Ksh[(lane + 32*i)*KS + 2*dp];
                    ffma2(acc2[0][ii], q2[0], k2, acc2[0][ii]);
                    ffma2(acc2[1][ii], q2[1], k2, acc2[1][ii]);
                    ffma2(acc2[2][ii], q2[2], k2, acc2[2][ii]);
                    ffma2(acc2[3][ii], q2[3], k2, acc2[3][ii]);
                }
            }
            #pragma unroll
            for (int r = 0; r < 4; r++)
                #pragma unroll
                for (int ii = 0; ii < 6; ii++)
                    Pw[r*N + lane + 32*(pass*6 + ii)] = hsum2(acc2[r][ii]);
        }

        // ---- softmax (reads raw logits from Pw, writes normalized probs) ----
        #pragma unroll
        for (int r = 0; r < 4; r++) {
            const float* brow = biasH + (size_t)(q0 + r)*N;
            float vals[12];
            float m = -3.0e38f;
            #pragma unroll
            for (int i = 0; i < 12; i++) {
                float v = mk[i] ? (Pw[r*N + lane + 32*i]*scale + brow[lane + 32*i])
                                : -1e9f;
                vals[i] = v;
                m = fmaxf(m, v);
            }
            #pragma unroll
            for (int o = 16; o; o >>= 1) m = fmaxf(m, __shfl_xor_sync(0xffffffffu, m, o));
            float s = 0.f;
            #pragma unroll
            for (int i = 0; i < 12; i++) { float e = __expf(vals[i] - m); vals[i] = e; s += e; }
            #pragma unroll
            for (int o = 16; o; o >>= 1) s += __shfl_xor_sync(0xffffffffu, s, o);
            float inv = 1.f / s;
            #pragma unroll
            for (int i = 0; i < 12; i++) Pw[r*N + lane + 32*i] = vals[i] * inv;
        }
        __syncwarp();

        // ---- PV: paired over k, V pre-packed ----
        ull o2[4] = {0ull, 0ull, 0ull, 0ull};
        #pragma unroll 2
        for (int k0 = 0; k0 < N; k0 += 4) {
            int k2a = k0 >> 1;
            ull va = V2[(size_t)k2a*VS2 + lane];
            ull vb = V2[(size_t)(k2a+1)*VS2 + lane];
            #pragma unroll
            for (int r = 0; r < 4; r++) {
                ulonglong2 pp = *(const ulonglong2*)&Pw[r*N + k0];
                ffma2(o2[r], pp.x, va, o2[r]);
                ffma2(o2[r], pp.y, vb, o2[r]);
            }
        }
        float* Og = g_o + ((size_t)b*N + q0)*C + h*DH + lane;
        #pragma unroll
        for (int r = 0; r < 4; r++) Og[r*C] = hsum2(o2[r]);
        __syncwarp();
    }
}

// ---------------------------------------------------------------------------
extern "C" void kernel_launch(void* const* d_in, const int* in_sizes, int n_in,
                              void* d_out, int out_size) {
    const float* pair   = (const float*)d_in[0];
    const int*   mask   = (const int*)  d_in[1];
    const float* ln_w   = (const float*)d_in[2];
    const float* ln_b   = (const float*)d_in[3];
    const float* w_bias = (const float*)d_in[4];
    const float* wq     = (const float*)d_in[5];
    const float* wk     = (const float*)d_in[6];
    const float* wv     = (const float*)d_in[7];
    const float* wg     = (const float*)d_in[8];
    const float* wo     = (const float*)d_in[9];

    float *gx, *gq, *gk, *gv, *gg, *go;
    cudaGetSymbolAddress((void**)&gx, g_x);
    cudaGetSymbolAddress((void**)&gq, g_q);
    cudaGetSymbolAddress((void**)&gk, g_k);
    cudaGetSymbolAddress((void**)&gv, g_v);
    cudaGetSymbolAddress((void**)&gg, g_g);
    cudaGetSymbolAddress((void**)&go, g_o);

    size_t gemm_smem = (size_t)(128*128 + 128*64) * sizeof(float);   // 96 KB
    size_t attn_smem = (size_t)(N*KS + 192*VS2*2 + 16*4*N + 16*128) * sizeof(float);
    cudaFuncSetAttribute(gemm_fused_kernel, cudaFuncAttributeMaxDynamicSharedMemorySize,
                         (int)gemm_smem);
    cudaFuncSetAttribute(attn_kernel, cudaFuncAttributeMaxDynamicSharedMemorySize,
                         (int)attn_smem);

    ln_bias_kernel<<<NN/8, 256>>>(pair, ln_w, ln_b, w_bias);

    // Fused Q/K/V/Gate projections (gate gets sigmoid: w index 3 -> bit 3)
    gemm_fused_kernel<<<NN/128, 256, gemm_smem>>>(
        gx, nullptr, wq, wk, wv, wg, gq, gk, gv, gg, 8, 8);

    attn_kernel<<<dim3(N, H), 512, attn_smem>>>(mask);

    // Output projection: (o * gate) @ wo
    gemm_fused_kernel<<<NN/128, 256, gemm_smem>>>(
        go, gg, wo, nullptr, nullptr, nullptr, (float*)d_out, nullptr, nullptr, nullptr, 2, 0);
}